// round 5
// baseline (speedup 1.0000x reference)
#include <cuda_runtime.h>
#include <math.h>
#include <stdint.h>

#define F    1024
#define NJ   64
#define C    256
#define HID  1024
#define H    8
#define D    128
#define M_TOT (NJ * F)      // 65536
#define EPSV 1e-6f

// Scratch (device globals — no allocation allowed in kernel_launch)
__device__ float g_Q[(size_t)M_TOT * HID];
__device__ float g_K[(size_t)M_TOT * HID];
__device__ float g_V[(size_t)M_TOT * HID];
__device__ float g_KV[(size_t)NJ * H * D * D];
__device__ float g_Ksum[(size_t)NJ * H * D];
__device__ float g_Xt[(size_t)M_TOT * C];        // x transposed/tf32/swizzled [m][k]
__device__ float g_Wt2[(size_t)3 * HID * C];     // W transposed/tf32/swizzled [w][ncol][k]

__device__ __forceinline__ float ftf32(float x) {
    float r;
    asm("cvt.rna.tf32.f32 %0, %1;" : "=f"(r) : "f"(x));
    return r;
}

__device__ __forceinline__ uint32_t smem_u32(const void* p) {
    uint32_t a;
    asm("{ .reg .u64 t; cvta.to.shared.u64 t, %1; cvt.u32.u64 %0, t; }"
        : "=r"(a) : "l"(p));
    return a;
}

__device__ __forceinline__ void cp16(uint32_t dst_smem, const void* src) {
    asm volatile("cp.async.cg.shared.global [%0], [%1], 16;"
                 :: "r"(dst_smem), "l"(__cvta_generic_to_global(src)) : "memory");
}
__device__ __forceinline__ void cp_commit() {
    asm volatile("cp.async.commit_group;" ::: "memory");
}
template <int N>
__device__ __forceinline__ void cp_wait() {
    asm volatile("cp.async.wait_group %0;" :: "n"(N) : "memory");
}

__device__ __forceinline__ void mma_tf32(float* c, const uint32_t* a,
                                         uint32_t b0, uint32_t b1) {
    asm volatile(
        "mma.sync.aligned.m16n8k8.row.col.f32.tf32.tf32.f32 "
        "{%0,%1,%2,%3}, {%4,%5,%6,%7}, {%8,%9}, {%0,%1,%2,%3};"
        : "+f"(c[0]), "+f"(c[1]), "+f"(c[2]), "+f"(c[3])
        : "r"(a[0]), "r"(a[1]), "r"(a[2]), "r"(a[3]), "r"(b0), "r"(b1));
}

// swizzled float index within a row of 256 k-values (row parity rp = row&7):
// idx(k) = (k>>5)*32 + (((k>>2)&7) ^ rp)*4 + (k&3)
__device__ __forceinline__ int swz_idx(int k, int rp) {
    return (k >> 5) * 32 + ((((k >> 2) & 7) ^ rp) << 2) + (k & 3);
}

// ---------------------------------------------------------------------------
// Prep A: x[f][n][c] -> g_Xt[m][k] (m = n*F+f), tf32-rounded, swizzled rows.
// 8 rows per block (one warp per row), lane covers k = lane*8 .. +7.
// ---------------------------------------------------------------------------
__global__ __launch_bounds__(256) void xprep_kernel(const float* __restrict__ x)
{
    const int warp = threadIdx.x >> 5, lane = threadIdx.x & 31;
    const int m = blockIdx.x * 8 + warp;
    const int f = m & (F - 1), n = m >> 10;
    const int rp = m & 7;
    const float* src = x + ((size_t)f * NJ + n) * C + lane * 8;
    float* dst = g_Xt + (size_t)m * C;

    float4 v0 = *(const float4*)(src);
    float4 v1 = *(const float4*)(src + 4);
    v0.x = ftf32(v0.x); v0.y = ftf32(v0.y); v0.z = ftf32(v0.z); v0.w = ftf32(v0.w);
    v1.x = ftf32(v1.x); v1.y = ftf32(v1.y); v1.z = ftf32(v1.z); v1.w = ftf32(v1.w);
    const int kt = lane >> 2;
    *(float4*)(dst + kt * 32 + ((((2 * lane) & 7) ^ rp) << 2))     = v0;
    *(float4*)(dst + kt * 32 + ((((2 * lane + 1) & 7) ^ rp) << 2)) = v1;
}

// ---------------------------------------------------------------------------
// Prep B: W[k][ncol] -> g_Wt2[w][ncol][k] tf32, swizzled rows (transpose).
// 32x32 tiles; each warp writes 4 output rows.
// ---------------------------------------------------------------------------
__global__ __launch_bounds__(256) void wprep_kernel(
    const float* __restrict__ Wq, const float* __restrict__ Wk,
    const float* __restrict__ Wv)
{
    __shared__ float t[32][33];
    const int w = blockIdx.z;
    const float* W = (w == 0) ? Wq : ((w == 1) ? Wk : Wv);
    const int k0 = blockIdx.x * 32, n0 = blockIdx.y * 32;
    const int lane = threadIdx.x & 31, warp = threadIdx.x >> 5;
    const int ty0 = threadIdx.x >> 5;
#pragma unroll
    for (int i = 0; i < 4; i++) {
        const int ky = ty0 + i * 8;
        t[ky][lane] = ftf32(W[(size_t)(k0 + ky) * HID + n0 + lane]);
    }
    __syncthreads();
#pragma unroll
    for (int i = 0; i < 4; i++) {
        const int nc = warp * 4 + i;
        const int ncol = n0 + nc;
        const float v = t[lane][nc];
        const int k = k0 + lane;
        g_Wt2[((size_t)w * HID + ncol) * C + (k >> 5) * 32 +
              ((((lane >> 2) & 7) ^ (ncol & 7)) << 2) + (lane & 3)] = v;
    }
}

// ---------------------------------------------------------------------------
// Kernel 1: QKV projection, mma.sync tf32, cp.async double-buffered.
// Block tile 128(M)x256(N), BK=32. 8 warps (2x4), warp tile 64x64.
// A/B smem: row-major 128B rows, granule-swizzled (matches global images).
// ---------------------------------------------------------------------------
__global__ __launch_bounds__(256, 1) void qkv_cp_kernel(
    const float* __restrict__ bq, const float* __restrict__ bk,
    const float* __restrict__ bv)
{
    extern __shared__ char dyn[];
    char* base = (char*)(((uintptr_t)dyn + 1023) & ~(uintptr_t)1023);
    // A0 @0 (16KB), A1 @16K, B0 @32K (32KB), B1 @64K
    const uint32_t sA[2] = {smem_u32(base), smem_u32(base + 16384)};
    const uint32_t sB[2] = {smem_u32(base + 32768), smem_u32(base + 65536)};

    const int tid  = threadIdx.x;
    const int lane = tid & 31;
    const int warp = tid >> 5;
    const int wm   = warp & 1;      // m offset wm*64
    const int wn   = warp >> 1;     // n offset wn*64
    const int gr   = lane >> 2;     // 0..7
    const int gc   = lane & 3;      // 0..3

    const int bm = blockIdx.x;      // 0..511
    const int by = blockIdx.y;      // 0..11
    const int w  = by >> 2;         // 0=Q,1=K,2=V
    const int ntile = by & 3;
    const int colbase = ntile * 256;

    // cp.async source/dst offsets (floats / bytes)
    // A: 4 chunks per thread: c = tid*4+i -> row c>>3, granule c&7
    const float* aSrc = g_Xt + (size_t)(bm * 128) * C;
    int aOffF[4]; uint32_t aOffS[4];
#pragma unroll
    for (int i = 0; i < 4; i++) {
        const int c = tid * 4 + i;
        aOffF[i] = (c >> 3) * C + (c & 7) * 4;
        aOffS[i] = (uint32_t)((c >> 3) * 128 + (c & 7) * 16);
    }
    // B: 8 chunks per thread: row = tid, granule = i
    const float* bSrc = g_Wt2 + ((size_t)w * HID + colbase + tid) * C;
    const uint32_t bOffS = (uint32_t)(tid * 128);

    float acc[4][8][4];
#pragma unroll
    for (int mf = 0; mf < 4; mf++)
#pragma unroll
        for (int nf = 0; nf < 8; nf++)
#pragma unroll
            for (int i = 0; i < 4; i++) acc[mf][nf][i] = 0.f;

    // prologue: ktile 0 -> buffer 0
#pragma unroll
    for (int i = 0; i < 4; i++) cp16(sA[0] + aOffS[i], aSrc + aOffF[i]);
#pragma unroll
    for (int i = 0; i < 8; i++) cp16(sB[0] + bOffS + i * 16, bSrc + i * 4);
    cp_commit();

    // fragment smem byte offsets (within buffer), per ks added later:
    // A value (mrow, k): mrow*128 + ((ksel ^ (mrow&7))<<4) + gc*4, ksel=(k>>2)&7
    for (int kt = 0; kt < 8; kt++) {
        const int b = kt & 1;
        if (kt < 7) {
            const int nb = b ^ 1;
            const int kf = (kt + 1) * 32;
#pragma unroll
            for (int i = 0; i < 4; i++) cp16(sA[nb] + aOffS[i], aSrc + kf + aOffF[i]);
#pragma unroll
            for (int i = 0; i < 8; i++) cp16(sB[nb] + bOffS + i * 16, bSrc + kf + i * 4);
            cp_commit();
            cp_wait<1>();
        } else {
            cp_wait<0>();
        }
        __syncthreads();

        const uint32_t aBuf = sA[b], bBuf = sB[b];
#pragma unroll
        for (int ks = 0; ks < 4; ks++) {
            const int ksel0 = ks * 2;         // (k>>2)&7 for k=kk+gc
            const int ksel1 = ks * 2 + 1;     // for k=kk+gc+4
            uint32_t afr[4][4];
#pragma unroll
            for (int mf = 0; mf < 4; mf++) {
                const int m0 = wm * 64 + mf * 16 + gr;   // and +8
                const uint32_t r0 = aBuf + (uint32_t)(m0 * 128 + gc * 4);
                const uint32_t r1 = aBuf + (uint32_t)((m0 + 8) * 128 + gc * 4);
                const uint32_t s0 = (uint32_t)(((ksel0 ^ gr) & 7) << 4);
                const uint32_t s1 = (uint32_t)(((ksel1 ^ gr) & 7) << 4);
                asm volatile("ld.shared.b32 %0, [%1];" : "=r"(afr[mf][0]) : "r"(r0 + s0));
                asm volatile("ld.shared.b32 %0, [%1];" : "=r"(afr[mf][1]) : "r"(r1 + s0));
                asm volatile("ld.shared.b32 %0, [%1];" : "=r"(afr[mf][2]) : "r"(r0 + s1));
                asm volatile("ld.shared.b32 %0, [%1];" : "=r"(afr[mf][3]) : "r"(r1 + s1));
            }
#pragma unroll
            for (int nf = 0; nf < 8; nf++) {
                const int n0 = wn * 64 + nf * 8 + gr;
                const uint32_t rb = bBuf + (uint32_t)(n0 * 128 + gc * 4);
                uint32_t b0, b1;
                asm volatile("ld.shared.b32 %0, [%1];" : "=r"(b0)
                             : "r"(rb + (uint32_t)(((ksel0 ^ gr) & 7) << 4)));
                asm volatile("ld.shared.b32 %0, [%1];" : "=r"(b1)
                             : "r"(rb + (uint32_t)(((ksel1 ^ gr) & 7) << 4)));
#pragma unroll
                for (int mf = 0; mf < 4; mf++)
                    mma_tf32(acc[mf][nf], afr[mf], b0, b1);
            }
        }
        if (kt < 7) __syncthreads();
    }

    // Epilogue: bias + feature map + stores
    const float* bias = (w == 0) ? bq : ((w == 1) ? bk : bv);
    float* OUT        = (w == 0) ? g_Q : ((w == 1) ? g_K : g_V);
    const bool fmap = (w < 2);
#pragma unroll
    for (int mf = 0; mf < 4; mf++) {
        const int mrow = bm * 128 + wm * 64 + mf * 16 + gr;
#pragma unroll
        for (int nf = 0; nf < 8; nf++) {
            const int col = colbase + wn * 64 + nf * 8 + 2 * gc;
            const float b0v = bias[col];
            const float b1v = bias[col + 1];
            float v0 = acc[mf][nf][0] + b0v;
            float v1 = acc[mf][nf][1] + b1v;
            float v2 = acc[mf][nf][2] + b0v;
            float v3 = acc[mf][nf][3] + b1v;
            if (fmap) {
                v0 = (v0 > 0.f) ? (v0 + 1.f) : __expf(v0);
                v1 = (v1 > 0.f) ? (v1 + 1.f) : __expf(v1);
                v2 = (v2 > 0.f) ? (v2 + 1.f) : __expf(v2);
                v3 = (v3 > 0.f) ? (v3 + 1.f) : __expf(v3);
            }
            *(float2*)&OUT[(size_t)mrow * HID + col]       = make_float2(v0, v1);
            *(float2*)&OUT[(size_t)(mrow + 8) * HID + col] = make_float2(v2, v3);
        }
    }
}

// ===================== kv / out kernels (unchanged, passing) =================
#define MMA_TILE_BODY(As, Bs, acc)                                            \
    _Pragma("unroll")                                                         \
    for (int ks = 0; ks < 4; ks++) {                                          \
        const int kk = ks * 8;                                                \
        uint32_t afr[2][4];                                                   \
        _Pragma("unroll")                                                     \
        for (int mf = 0; mf < 2; mf++) {                                      \
            const int m0 = wm2 * 32 + mf * 16;                                \
            afr[mf][0] = __float_as_uint(As[kk + gc][m0 + gr]);               \
            afr[mf][1] = __float_as_uint(As[kk + gc][m0 + gr + 8]);           \
            afr[mf][2] = __float_as_uint(As[kk + gc + 4][m0 + gr]);           \
            afr[mf][3] = __float_as_uint(As[kk + gc + 4][m0 + gr + 8]);       \
        }                                                                     \
        _Pragma("unroll")                                                     \
        for (int nf = 0; nf < 8; nf++) {                                      \
            const int n0 = wn2 * 64 + nf * 8;                                 \
            const uint32_t b0 = __float_as_uint(Bs[kk + gc][n0 + gr]);        \
            const uint32_t b1 = __float_as_uint(Bs[kk + gc + 4][n0 + gr]);    \
            mma_tf32(acc[0][nf], afr[0], b0, b1);                             \
            mma_tf32(acc[1][nf], afr[1], b0, b1);                             \
        }                                                                     \
    }

__global__ __launch_bounds__(256) void kv_mma_kernel()
{
    __shared__ float As[32][136];
    __shared__ float Bs[32][136];
    __shared__ float sKsum[128];

    const int tid  = threadIdx.x;
    const int lane = tid & 31;
    const int warp = tid >> 5;
    const int wm2  = warp & 3;
    const int wn2  = warp >> 2;
    const int gr   = lane >> 2;
    const int gc   = lane & 3;

    const int n = blockIdx.x, h = blockIdx.y;
    const size_t base = (size_t)n * F * HID + (size_t)h * D;

    const int sr = tid >> 3;
    const int c0 = (tid & 7) * 4;
    const float* vptr = g_V + base + (size_t)sr * HID + c0;
    const float* kptr = g_K + base + (size_t)sr * HID + c0;

    if (tid < 128) sKsum[tid] = 0.f;
    float4 kacc[4];
#pragma unroll
    for (int i = 0; i < 4; i++) kacc[i] = make_float4(0.f, 0.f, 0.f, 0.f);

    float acc[2][8][4];
#pragma unroll
    for (int mf = 0; mf < 2; mf++)
#pragma unroll
        for (int nf = 0; nf < 8; nf++)
#pragma unroll
            for (int i = 0; i < 4; i++) acc[mf][nf][i] = 0.f;

    for (int s0 = 0; s0 < F; s0 += 32) {
        float4 av[4], ak[4];
#pragma unroll
        for (int i = 0; i < 4; i++) {
            av[i] = *(const float4*)(vptr + (size_t)s0 * HID + i * 32);
            ak[i] = *(const float4*)(kptr + (size_t)s0 * HID + i * 32);
        }
        __syncthreads();
#pragma unroll
        for (int i = 0; i < 4; i++) {
            float4 tv = av[i], tk = ak[i];
            kacc[i].x += tk.x; kacc[i].y += tk.y; kacc[i].z += tk.z; kacc[i].w += tk.w;
            tv.x = ftf32(tv.x); tv.y = ftf32(tv.y); tv.z = ftf32(tv.z); tv.w = ftf32(tv.w);
            tk.x = ftf32(tk.x); tk.y = ftf32(tk.y); tk.z = ftf32(tk.z); tk.w = ftf32(tk.w);
            *(float4*)&As[sr][c0 + i * 32] = tv;
            *(float4*)&Bs[sr][c0 + i * 32] = tk;
        }
        __syncthreads();

        MMA_TILE_BODY(As, Bs, acc)
    }

#pragma unroll
    for (int i = 0; i < 4; i++) {
        atomicAdd(&sKsum[c0 + i * 32 + 0], kacc[i].x);
        atomicAdd(&sKsum[c0 + i * 32 + 1], kacc[i].y);
        atomicAdd(&sKsum[c0 + i * 32 + 2], kacc[i].z);
        atomicAdd(&sKsum[c0 + i * 32 + 3], kacc[i].w);
    }
    __syncthreads();

    const size_t nh = (size_t)n * H + h;
    if (tid < 128) g_Ksum[nh * D + tid] = sKsum[tid];

    const size_t kvbase = nh * D * D;
#pragma unroll
    for (int mf = 0; mf < 2; mf++) {
        const int mrow = wm2 * 32 + mf * 16 + gr;
#pragma unroll
        for (int nf = 0; nf < 8; nf++) {
            const int ncol = wn2 * 64 + nf * 8 + 2 * gc;
            *(float2*)&g_KV[kvbase + (size_t)mrow * D + ncol] =
                make_float2(acc[mf][nf][0], acc[mf][nf][1]);
            *(float2*)&g_KV[kvbase + (size_t)(mrow + 8) * D + ncol] =
                make_float2(acc[mf][nf][2], acc[mf][nf][3]);
        }
    }
}

__global__ __launch_bounds__(256) void out_mma_kernel(float* __restrict__ out)
{
    __shared__ float As[32][136];
    __shared__ float Bs[32][136];
    __shared__ float sZ[128];
    __shared__ float sKs[128];

    const int tid  = threadIdx.x;
    const int lane = tid & 31;
    const int warp = tid >> 5;
    const int wm2  = warp & 3;
    const int wn2  = warp >> 2;
    const int gr   = lane >> 2;
    const int gc   = lane & 3;

    const int lt = blockIdx.x, n = blockIdx.y, h = blockIdx.z;
    const int l0 = lt * 128;
    const size_t nh = (size_t)n * H + h;
    const size_t qbase  = ((size_t)n * F + l0) * HID + (size_t)h * D;
    const size_t kvbase = nh * D * D;

    if (tid < 128) sKs[tid] = g_Ksum[nh * D + tid];
    __syncthreads();

    {
        float4 kv4 = *(const float4*)&sKs[lane * 4];
#pragma unroll
        for (int r8 = 0; r8 < 16; r8++) {
            const int row = warp * 16 + r8;
            const float* q = g_Q + qbase + (size_t)row * HID;
            float4 qv = *(const float4*)(q + lane * 4);
            float d = qv.x * kv4.x + qv.y * kv4.y + qv.z * kv4.z + qv.w * kv4.w;
#pragma unroll
            for (int off = 16; off; off >>= 1) d += __shfl_xor_sync(0xffffffffu, d, off);
            if (lane == 0) sZ[row] = 1.f / (d + EPSV);
        }
    }

    const int lr  = tid >> 1;
    const int d16 = (tid & 1) * 16;
    const float* qp  = g_Q + qbase + (size_t)lr * HID + d16;
    const float* kvp = g_KV + kvbase + (size_t)lr * D + d16;

    float acc[2][8][4];
#pragma unroll
    for (int mf = 0; mf < 2; mf++)
#pragma unroll
        for (int nf = 0; nf < 8; nf++)
#pragma unroll
            for (int i = 0; i < 4; i++) acc[mf][nf][i] = 0.f;

    for (int d0 = 0; d0 < D; d0 += 32) {
        float4 aR[4], bR[4];
#pragma unroll
        for (int i = 0; i < 4; i++) {
            aR[i] = *(const float4*)(qp + d0 + i * 4);
            bR[i] = *(const float4*)(kvp + d0 + i * 4);
        }
        __syncthreads();
#pragma unroll
        for (int i = 0; i < 4; i++) {
            const int kb = d16 + i * 4;
            As[kb + 0][lr] = ftf32(aR[i].x);
            As[kb + 1][lr] = ftf32(aR[i].y);
            As[kb + 2][lr] = ftf32(aR[i].z);
            As[kb + 3][lr] = ftf32(aR[i].w);
            Bs[kb + 0][lr] = ftf32(bR[i].x);
            Bs[kb + 1][lr] = ftf32(bR[i].y);
            Bs[kb + 2][lr] = ftf32(bR[i].z);
            Bs[kb + 3][lr] = ftf32(bR[i].w);
        }
        __syncthreads();

        MMA_TILE_BODY(As, Bs, acc)
    }

#pragma unroll
    for (int mf = 0; mf < 2; mf++) {
        const int row = wm2 * 32 + mf * 16 + gr;
        const float z0 = sZ[row];
        const float z1 = sZ[row + 8];
        const size_t ob0 = (size_t)(l0 + row) * (NJ * HID) + (size_t)n * HID + (size_t)h * D;
        const size_t ob1 = (size_t)(l0 + row + 8) * (NJ * HID) + (size_t)n * HID + (size_t)h * D;
#pragma unroll
        for (int nf = 0; nf < 8; nf++) {
            const int ncol = wn2 * 64 + nf * 8 + 2 * gc;
            *(float2*)&out[ob0 + ncol] =
                make_float2(acc[mf][nf][0] * z0, acc[mf][nf][1] * z0);
            *(float2*)&out[ob1 + ncol] =
                make_float2(acc[mf][nf][2] * z1, acc[mf][nf][3] * z1);
        }
    }
}

// ---------------------------------------------------------------------------
extern "C" void kernel_launch(void* const* d_in, const int* in_sizes, int n_in,
                              void* d_out, int out_size)
{
    const float* x  = (const float*)d_in[0];
    const float* Wq = (const float*)d_in[1];
    const float* bq = (const float*)d_in[2];
    const float* Wk = (const float*)d_in[3];
    const float* bk = (const float*)d_in[4];
    const float* Wv = (const float*)d_in[5];
    const float* bv = (const float*)d_in[6];
    float* out = (float*)d_out;

    // Prep: transposed/tf32/swizzled staging images
    xprep_kernel<<<M_TOT / 8, 256>>>(x);
    dim3 gw(C / 32, HID / 32, 3);
    wprep_kernel<<<gw, 256>>>(Wq, Wk, Wv);

    // QKV projection (cp.async + mma.sync tf32)
    const int smem = 99328;   // 96KB buffers + 1KB alignment slack
    cudaFuncSetAttribute(qkv_cp_kernel,
                         cudaFuncAttributeMaxDynamicSharedMemorySize, smem);
    dim3 g1(M_TOT / 128, 12);
    qkv_cp_kernel<<<g1, 256, smem>>>(bq, bk, bv);

    dim3 g2(NJ, H);
    kv_mma_kernel<<<g2, 256>>>();

    dim3 g3(F / 128, NJ, H);
    out_mma_kernel<<<g3, 256>>>(out);
}

// round 7
// speedup vs baseline: 1.1161x; 1.1161x over previous
#include <cuda_runtime.h>
#include <math.h>
#include <stdint.h>

#define F    1024
#define NJ   64
#define C    256
#define HID  1024
#define H    8
#define D    128
#define M_TOT (NJ * F)      // 65536
#define EPSV 1e-6f

// Scratch (device globals — no allocation allowed in kernel_launch)
__device__ float g_Q[(size_t)M_TOT * HID];
__device__ float g_K[(size_t)M_TOT * HID];
__device__ float g_V[(size_t)M_TOT * HID];
__device__ float g_KV[(size_t)NJ * H * D * D];
__device__ float g_Ksum[(size_t)NJ * H * D];
__device__ float g_Wr[(size_t)3 * C * HID];   // tf32-rounded weights, native [k][n] layout

__device__ __forceinline__ float ftf32(float x) {
    float r;
    asm("cvt.rna.tf32.f32 %0, %1;" : "=f"(r) : "f"(x));
    return r;
}

__device__ __forceinline__ uint32_t smem_u32(const void* p) {
    uint32_t a;
    asm("{ .reg .u64 t; cvta.to.shared.u64 t, %1; cvt.u32.u64 %0, t; }"
        : "=r"(a) : "l"(p));
    return a;
}

__device__ __forceinline__ void cp16(uint32_t dst_smem, const void* src) {
    asm volatile("cp.async.cg.shared.global [%0], [%1], 16;"
                 :: "r"(dst_smem), "l"(__cvta_generic_to_global(src)) : "memory");
}
__device__ __forceinline__ void cp_commit() {
    asm volatile("cp.async.commit_group;" ::: "memory");
}
__device__ __forceinline__ void cp_wait0() {
    asm volatile("cp.async.wait_group 0;" ::: "memory");
}

__device__ __forceinline__ void mma_tf32(float* c, const uint32_t* a,
                                         uint32_t b0, uint32_t b1) {
    asm volatile(
        "mma.sync.aligned.m16n8k8.row.col.f32.tf32.tf32.f32 "
        "{%0,%1,%2,%3}, {%4,%5,%6,%7}, {%8,%9}, {%0,%1,%2,%3};"
        : "+f"(c[0]), "+f"(c[1]), "+f"(c[2]), "+f"(c[3])
        : "r"(a[0]), "r"(a[1]), "r"(a[2]), "r"(a[3]), "r"(b0), "r"(b1));
}

// ---------------------------------------------------------------------------
// Prep: g_Wr = ftf32(W), same layout (Q,K,V concatenated).
// ---------------------------------------------------------------------------
__global__ __launch_bounds__(256) void wr_kernel(
    const float* __restrict__ Wq, const float* __restrict__ Wk,
    const float* __restrict__ Wv)
{
    const size_t elems = (size_t)C * HID;
    const size_t i4 = (size_t)blockIdx.x * 256 + threadIdx.x;
    const size_t per = elems / 4;
    const int w = (int)(i4 / per);
    const size_t off = (i4 % per) * 4;
    const float* W = (w == 0) ? Wq : ((w == 1) ? Wk : Wv);
    float4 v = *(const float4*)(W + off);
    v.x = ftf32(v.x); v.y = ftf32(v.y); v.z = ftf32(v.z); v.w = ftf32(v.w);
    *(float4*)(g_Wr + (size_t)w * elems + off) = v;
}

// ---------------------------------------------------------------------------
// Kernel 1: QKV projection, tf32 mma.sync, block tile 128(M)x256(N), BK=32.
// 8 warps (2 m x 4 n), warp tile 64x64. A: LDG+ftf32+STS; B: cp.async from g_Wr.
// ---------------------------------------------------------------------------
__global__ __launch_bounds__(256) void qkv_mma_kernel(
    const float* __restrict__ x,
    const float* __restrict__ bq, const float* __restrict__ bk,
    const float* __restrict__ bv)
{
    extern __shared__ float smem[];
    float (*As)[136] = (float(*)[136])smem;              // 32 x 136
    float (*Bs)[264] = (float(*)[264])(smem + 32 * 136); // 32 x 264
    const uint32_t sB = smem_u32(&Bs[0][0]);

    const int tid  = threadIdx.x;
    const int lane = tid & 31;
    const int warp = tid >> 5;
    const int wm   = warp & 1;      // m offset wm*64
    const int wn   = warp >> 1;     // n offset wn*64
    const int gr   = lane >> 2;
    const int gc   = lane & 3;

    const int bm = blockIdx.x;      // 0..511
    const int by = blockIdx.y;      // 0..11
    const int w  = by >> 2;         // 0=Q,1=K,2=V
    const int colbase = (by & 3) * 256;

    // A loader: row ar (0..127), half kq, 16 k-floats
    const int ar   = tid >> 1;
    const int kq   = tid & 1;
    const int am   = bm * 128 + ar;
    const int fidx = am & (F - 1);
    const int nidx = am >> 10;
    const float* ap = x + ((size_t)fidx * NJ + nidx) * C + kq * 16;

    // B cp.async: 2048 chunks per ktile; c = i*256 + tid (i<8) -> warp-contiguous
    // row = c>>6 (0..31), seg = (c&63)*4 (0..252 floats)
    const float* bsrc = g_Wr + (size_t)w * C * HID + colbase;
    int brow[8]; int bseg[8]; uint32_t bdst[8];
#pragma unroll
    for (int i = 0; i < 8; i++) {
        const int c = i * 256 + tid;
        brow[i] = c >> 6;
        bseg[i] = (c & 63) * 4;
        bdst[i] = sB + (uint32_t)(brow[i] * 264 + bseg[i]) * 4;
    }

    float acc[4][8][4];
#pragma unroll
    for (int mf = 0; mf < 4; mf++)
#pragma unroll
        for (int nf = 0; nf < 8; nf++)
#pragma unroll
            for (int i = 0; i < 4; i++) acc[mf][nf][i] = 0.f;

    // prefetch A ktile 0
    float4 aR[4];
#pragma unroll
    for (int i = 0; i < 4; i++) aR[i] = *(const float4*)(ap + i * 4);

    for (int kt = 0; kt < 8; kt++) {
        __syncthreads();   // previous compute done; buffers free
#pragma unroll
        for (int i = 0; i < 8; i++)
            cp16(bdst[i], bsrc + (size_t)(kt * 32 + brow[i]) * HID + bseg[i]);
        cp_commit();
#pragma unroll
        for (int i = 0; i < 4; i++) {
            const int kb = kq * 16 + i * 4;
            As[kb + 0][ar] = ftf32(aR[i].x);
            As[kb + 1][ar] = ftf32(aR[i].y);
            As[kb + 2][ar] = ftf32(aR[i].z);
            As[kb + 3][ar] = ftf32(aR[i].w);
        }
        if (kt < 7) {
#pragma unroll
            for (int i = 0; i < 4; i++)
                aR[i] = *(const float4*)(ap + (kt + 1) * 32 + i * 4);
        }
        cp_wait0();
        __syncthreads();

#pragma unroll
        for (int ks = 0; ks < 4; ks++) {
            const int kk = ks * 8;
            uint32_t afr[4][4];
#pragma unroll
            for (int mf = 0; mf < 4; mf++) {
                const int m0 = wm * 64 + mf * 16;
                afr[mf][0] = __float_as_uint(As[kk + gc][m0 + gr]);
                afr[mf][1] = __float_as_uint(As[kk + gc][m0 + gr + 8]);
                afr[mf][2] = __float_as_uint(As[kk + gc + 4][m0 + gr]);
                afr[mf][3] = __float_as_uint(As[kk + gc + 4][m0 + gr + 8]);
            }
#pragma unroll
            for (int nf = 0; nf < 8; nf++) {
                const int n0 = wn * 64 + nf * 8;
                const uint32_t b0 = __float_as_uint(Bs[kk + gc][n0 + gr]);
                const uint32_t b1 = __float_as_uint(Bs[kk + gc + 4][n0 + gr]);
#pragma unroll
                for (int mf = 0; mf < 4; mf++)
                    mma_tf32(acc[mf][nf], afr[mf], b0, b1);
            }
        }
    }

    // Epilogue: bias + feature map
    const float* bias = (w == 0) ? bq : ((w == 1) ? bk : bv);
    float* OUT        = (w == 0) ? g_Q : ((w == 1) ? g_K : g_V);
    const bool fmap = (w < 2);
#pragma unroll
    for (int mf = 0; mf < 4; mf++) {
        const int mrow = bm * 128 + wm * 64 + mf * 16 + gr;
#pragma unroll
        for (int nf = 0; nf < 8; nf++) {
            const int col = colbase + wn * 64 + nf * 8 + 2 * gc;
            const float b0v = bias[col];
            const float b1v = bias[col + 1];
            float v0 = acc[mf][nf][0] + b0v;
            float v1 = acc[mf][nf][1] + b1v;
            float v2 = acc[mf][nf][2] + b0v;
            float v3 = acc[mf][nf][3] + b1v;
            if (fmap) {
                v0 = (v0 > 0.f) ? (v0 + 1.f) : __expf(v0);
                v1 = (v1 > 0.f) ? (v1 + 1.f) : __expf(v1);
                v2 = (v2 > 0.f) ? (v2 + 1.f) : __expf(v2);
                v3 = (v3 > 0.f) ? (v3 + 1.f) : __expf(v3);
            }
            *(float2*)&OUT[(size_t)mrow * HID + col]       = make_float2(v0, v1);
            *(float2*)&OUT[(size_t)(mrow + 8) * HID + col] = make_float2(v2, v3);
        }
    }
}

// ===================== kv / out kernels (R3, proven) =========================
#define MMA_TILE_BODY(As, Bs, acc)                                            \
    _Pragma("unroll")                                                         \
    for (int ks = 0; ks < 4; ks++) {                                          \
        const int kk = ks * 8;                                                \
        uint32_t afr[2][4];                                                   \
        _Pragma("unroll")                                                     \
        for (int mf = 0; mf < 2; mf++) {                                      \
            const int m0 = wm2 * 32 + mf * 16;                                \
            afr[mf][0] = __float_as_uint(As[kk + gc][m0 + gr]);               \
            afr[mf][1] = __float_as_uint(As[kk + gc][m0 + gr + 8]);           \
            afr[mf][2] = __float_as_uint(As[kk + gc + 4][m0 + gr]);           \
            afr[mf][3] = __float_as_uint(As[kk + gc + 4][m0 + gr + 8]);       \
        }                                                                     \
        _Pragma("unroll")                                                     \
        for (int nf = 0; nf < 8; nf++) {                                      \
            const int n0 = wn2 * 64 + nf * 8;                                 \
            const uint32_t b0 = __float_as_uint(Bs[kk + gc][n0 + gr]);        \
            const uint32_t b1 = __float_as_uint(Bs[kk + gc + 4][n0 + gr]);    \
            mma_tf32(acc[0][nf], afr[0], b0, b1);                             \
            mma_tf32(acc[1][nf], afr[1], b0, b1);                             \
        }                                                                     \
    }

__global__ __launch_bounds__(256) void kv_mma_kernel()
{
    __shared__ float As[32][136];
    __shared__ float Bs[32][136];
    __shared__ float sKsum[128];

    const int tid  = threadIdx.x;
    const int lane = tid & 31;
    const int warp = tid >> 5;
    const int wm2  = warp & 3;
    const int wn2  = warp >> 2;
    const int gr   = lane >> 2;
    const int gc   = lane & 3;

    const int n = blockIdx.x, h = blockIdx.y;
    const size_t base = (size_t)n * F * HID + (size_t)h * D;

    const int sr = tid >> 3;
    const int c0 = (tid & 7) * 4;
    const float* vptr = g_V + base + (size_t)sr * HID + c0;
    const float* kptr = g_K + base + (size_t)sr * HID + c0;

    if (tid < 128) sKsum[tid] = 0.f;
    float4 kacc[4];
#pragma unroll
    for (int i = 0; i < 4; i++) kacc[i] = make_float4(0.f, 0.f, 0.f, 0.f);

    float acc[2][8][4];
#pragma unroll
    for (int mf = 0; mf < 2; mf++)
#pragma unroll
        for (int nf = 0; nf < 8; nf++)
#pragma unroll
            for (int i = 0; i < 4; i++) acc[mf][nf][i] = 0.f;

    for (int s0 = 0; s0 < F; s0 += 32) {
        float4 av[4], ak[4];
#pragma unroll
        for (int i = 0; i < 4; i++) {
            av[i] = *(const float4*)(vptr + (size_t)s0 * HID + i * 32);
            ak[i] = *(const float4*)(kptr + (size_t)s0 * HID + i * 32);
        }
        __syncthreads();
#pragma unroll
        for (int i = 0; i < 4; i++) {
            float4 tv = av[i], tk = ak[i];
            kacc[i].x += tk.x; kacc[i].y += tk.y; kacc[i].z += tk.z; kacc[i].w += tk.w;
            tv.x = ftf32(tv.x); tv.y = ftf32(tv.y); tv.z = ftf32(tv.z); tv.w = ftf32(tv.w);
            tk.x = ftf32(tk.x); tk.y = ftf32(tk.y); tk.z = ftf32(tk.z); tk.w = ftf32(tk.w);
            *(float4*)&As[sr][c0 + i * 32] = tv;
            *(float4*)&Bs[sr][c0 + i * 32] = tk;
        }
        __syncthreads();

        MMA_TILE_BODY(As, Bs, acc)
    }

#pragma unroll
    for (int i = 0; i < 4; i++) {
        atomicAdd(&sKsum[c0 + i * 32 + 0], kacc[i].x);
        atomicAdd(&sKsum[c0 + i * 32 + 1], kacc[i].y);
        atomicAdd(&sKsum[c0 + i * 32 + 2], kacc[i].z);
        atomicAdd(&sKsum[c0 + i * 32 + 3], kacc[i].w);
    }
    __syncthreads();

    const size_t nh = (size_t)n * H + h;
    if (tid < 128) g_Ksum[nh * D + tid] = sKsum[tid];

    const size_t kvbase = nh * D * D;
#pragma unroll
    for (int mf = 0; mf < 2; mf++) {
        const int mrow = wm2 * 32 + mf * 16 + gr;
#pragma unroll
        for (int nf = 0; nf < 8; nf++) {
            const int ncol = wn2 * 64 + nf * 8 + 2 * gc;
            *(float2*)&g_KV[kvbase + (size_t)mrow * D + ncol] =
                make_float2(acc[mf][nf][0], acc[mf][nf][1]);
            *(float2*)&g_KV[kvbase + (size_t)(mrow + 8) * D + ncol] =
                make_float2(acc[mf][nf][2], acc[mf][nf][3]);
        }
    }
}

__global__ __launch_bounds__(256) void out_mma_kernel(float* __restrict__ out)
{
    __shared__ float As[32][136];
    __shared__ float Bs[32][136];
    __shared__ float sZ[128];
    __shared__ float sKs[128];

    const int tid  = threadIdx.x;
    const int lane = tid & 31;
    const int warp = tid >> 5;
    const int wm2  = warp & 3;
    const int wn2  = warp >> 2;
    const int gr   = lane >> 2;
    const int gc   = lane & 3;

    const int lt = blockIdx.x, n = blockIdx.y, h = blockIdx.z;
    const int l0 = lt * 128;
    const size_t nh = (size_t)n * H + h;
    const size_t qbase  = ((size_t)n * F + l0) * HID + (size_t)h * D;
    const size_t kvbase = nh * D * D;

    if (tid < 128) sKs[tid] = g_Ksum[nh * D + tid];
    __syncthreads();

    {
        float4 kv4 = *(const float4*)&sKs[lane * 4];
#pragma unroll
        for (int r8 = 0; r8 < 16; r8++) {
            const int row = warp * 16 + r8;
            const float* q = g_Q + qbase + (size_t)row * HID;
            float4 qv = *(const float4*)(q + lane * 4);
            float d = qv.x * kv4.x + qv.y * kv4.y + qv.z * kv4.z + qv.w * kv4.w;
#pragma unroll
            for (int off = 16; off; off >>= 1) d += __shfl_xor_sync(0xffffffffu, d, off);
            if (lane == 0) sZ[row] = 1.f / (d + EPSV);
        }
    }

    const int lr  = tid >> 1;
    const int d16 = (tid & 1) * 16;
    const float* qp  = g_Q + qbase + (size_t)lr * HID + d16;
    const float* kvp = g_KV + kvbase + (size_t)lr * D + d16;

    float acc[2][8][4];
#pragma unroll
    for (int mf = 0; mf < 2; mf++)
#pragma unroll
        for (int nf = 0; nf < 8; nf++)
#pragma unroll
            for (int i = 0; i < 4; i++) acc[mf][nf][i] = 0.f;

    for (int d0 = 0; d0 < D; d0 += 32) {
        float4 aR[4], bR[4];
#pragma unroll
        for (int i = 0; i < 4; i++) {
            aR[i] = *(const float4*)(qp + d0 + i * 4);
            bR[i] = *(const float4*)(kvp + d0 + i * 4);
        }
        __syncthreads();
#pragma unroll
        for (int i = 0; i < 4; i++) {
            const int kb = d16 + i * 4;
            As[kb + 0][lr] = ftf32(aR[i].x);
            As[kb + 1][lr] = ftf32(aR[i].y);
            As[kb + 2][lr] = ftf32(aR[i].z);
            As[kb + 3][lr] = ftf32(aR[i].w);
            Bs[kb + 0][lr] = ftf32(bR[i].x);
            Bs[kb + 1][lr] = ftf32(bR[i].y);
            Bs[kb + 2][lr] = ftf32(bR[i].z);
            Bs[kb + 3][lr] = ftf32(bR[i].w);
        }
        __syncthreads();

        MMA_TILE_BODY(As, Bs, acc)
    }

#pragma unroll
    for (int mf = 0; mf < 2; mf++) {
        const int row = wm2 * 32 + mf * 16 + gr;
        const float z0 = sZ[row];
        const float z1 = sZ[row + 8];
        const size_t ob0 = (size_t)(l0 + row) * (NJ * HID) + (size_t)n * HID + (size_t)h * D;
        const size_t ob1 = (size_t)(l0 + row + 8) * (NJ * HID) + (size_t)n * HID + (size_t)h * D;
#pragma unroll
        for (int nf = 0; nf < 8; nf++) {
            const int ncol = wn2 * 64 + nf * 8 + 2 * gc;
            *(float2*)&out[ob0 + ncol] =
                make_float2(acc[mf][nf][0] * z0, acc[mf][nf][1] * z0);
            *(float2*)&out[ob1 + ncol] =
                make_float2(acc[mf][nf][2] * z1, acc[mf][nf][3] * z1);
        }
    }
}

// ---------------------------------------------------------------------------
extern "C" void kernel_launch(void* const* d_in, const int* in_sizes, int n_in,
                              void* d_out, int out_size)
{
    const float* x  = (const float*)d_in[0];
    const float* Wq = (const float*)d_in[1];
    const float* bq = (const float*)d_in[2];
    const float* Wk = (const float*)d_in[3];
    const float* bk = (const float*)d_in[4];
    const float* Wv = (const float*)d_in[5];
    const float* bv = (const float*)d_in[6];
    float* out = (float*)d_out;

    // Prep: tf32-rounded weights (same layout)
    wr_kernel<<<3 * C * HID / 4 / 256, 256>>>(Wq, Wk, Wv);

    // QKV projection: 128x256 block tile
    const int smem = (32 * 136 + 32 * 264) * 4;   // 51200 B
    cudaFuncSetAttribute(qkv_mma_kernel,
                         cudaFuncAttributeMaxDynamicSharedMemorySize, smem);
    dim3 g1(M_TOT / 128, 12);
    qkv_mma_kernel<<<g1, 256, smem>>>(x, bq, bk, bv);

    dim3 g2(NJ, H);
    kv_mma_kernel<<<g2, 256>>>();

    dim3 g3(F / 128, NJ, H);
    out_mma_kernel<<<g3, 256>>>(out);
}